// round 1
// baseline (speedup 1.0000x reference)
#include <cuda_runtime.h>

// ---------------------------------------------------------------------------
// SSIM fused kernel for (16,3,512,512) fp32 pairs on sm_100a.
// Separable 11-tap Gaussian (sigma=1.5), 5 convolved quantities, pointwise
// SSIM, global mean.
// ---------------------------------------------------------------------------

#define IMG_H 512
#define IMG_W 512
#define TW 64          // output tile width
#define TH 32          // output tile height
#define HALO 5
#define IW (TW + 10)   // 74
#define IH (TH + 10)   // 42
#define PITCH 75       // smem row pitch in floats (gcd(75,32)=1 -> conflict-free y strides)
#define NTHREADS 256

// ---- compile-time Gaussian weights, double precision (match numpy) --------
constexpr double expser(double x) {   // exp(x), x >= 0, positive series (no cancellation)
    double t = 1.0, s = 1.0;
    for (int k = 1; k < 100; k++) { t = t * x / (double)k; s += t; }
    return s;
}
constexpr double gk(int i) { double d = (double)(i - 5); return 1.0 / expser(d * d / 4.5); }
constexpr double GSUM = gk(0)+gk(1)+gk(2)+gk(3)+gk(4)+gk(5)+gk(6)+gk(7)+gk(8)+gk(9)+gk(10);
constexpr float WF(int i) { return (float)(gk(i) / GSUM); }
__device__ constexpr float W[11] = {WF(0),WF(1),WF(2),WF(3),WF(4),WF(5),
                                    WF(6),WF(7),WF(8),WF(9),WF(10)};

__device__ double g_sum;

__global__ void ssim_zero() { g_sum = 0.0; }

__global__ void ssim_final(float* out, double inv_n) {
    out[0] = (float)(g_sum * inv_n);
}

// vertical pass for one quantity Q at one smem column, 8-row output strip
template <int Q>
__device__ __forceinline__ void vpass(const float* __restrict__ s1,
                                      const float* __restrict__ s2,
                                      float* __restrict__ out) {
    float acc[8];
#pragma unroll
    for (int k = 0; k < 8; k++) acc[k] = 0.0f;
#pragma unroll
    for (int j = 0; j < 18; j++) {
        float v;
        if (Q == 0) { v = s1[j * PITCH]; }
        else if (Q == 1) { v = s2[j * PITCH]; }
        else if (Q == 2) { float a = s1[j * PITCH]; v = a * a; }
        else if (Q == 3) { float b = s2[j * PITCH]; v = b * b; }
        else            { v = s1[j * PITCH] * s2[j * PITCH]; }
#pragma unroll
        for (int k = 0; k < 8; k++) {
            int w = j - k;
            if (w >= 0 && w < 11) acc[k] = fmaf(W[w], v, acc[k]);
        }
    }
#pragma unroll
    for (int k = 0; k < 8; k++) out[k * PITCH] = acc[k];
}

__global__ __launch_bounds__(NTHREADS, 2)
void ssim_main(const float* __restrict__ img1, const float* __restrict__ img2) {
    extern __shared__ float sm[];
    float* sI1 = sm;                          // IH * PITCH
    float* sI2 = sm + IH * PITCH;             // IH * PITCH
    float* sCS = sm + 2 * IH * PITCH;         // 5 * TH * PITCH
    __shared__ double sRed[NTHREADS / 32];

    const int tid = threadIdx.x;
    const int plane = blockIdx.z;
    const int ty0 = blockIdx.y * TH;
    const int tx0 = blockIdx.x * TW;
    const float* p1 = img1 + (size_t)plane * (IMG_H * IMG_W);
    const float* p2 = img2 + (size_t)plane * (IMG_H * IMG_W);

    // -------- phase 1: load halo'd tile of both images (zero-pad OOB) ------
    for (int i = tid; i < IH * IW; i += NTHREADS) {
        int ly = i / IW;
        int lx = i - ly * IW;
        int gy = ty0 - HALO + ly;
        int gx = tx0 - HALO + lx;
        float a = 0.0f, b = 0.0f;
        if ((unsigned)gy < (unsigned)IMG_H && (unsigned)gx < (unsigned)IMG_W) {
            int g = gy * IMG_W + gx;
            a = p1[g];
            b = p2[g];
        }
        sI1[ly * PITCH + lx] = a;
        sI2[ly * PITCH + lx] = b;
    }
    __syncthreads();

    // -------- phase 2: vertical conv of 5 quantities -> column sums --------
    // tasks: x in [0,74) X ystrip in {0,8,16,24} X q in [0,5)  = 1480
    for (int t = tid; t < 5 * 4 * IW; t += NTHREADS) {
        int x = t % IW;
        int r = t / IW;              // 0..19
        int ys = (r & 3) * 8;
        int q = r >> 2;
        const float* s1 = &sI1[ys * PITCH + x];
        const float* s2 = &sI2[ys * PITCH + x];
        float* out = &sCS[(q * TH + ys) * PITCH + x];
        switch (q) {
            case 0: vpass<0>(s1, s2, out); break;
            case 1: vpass<1>(s1, s2, out); break;
            case 2: vpass<2>(s1, s2, out); break;
            case 3: vpass<3>(s1, s2, out); break;
            default: vpass<4>(s1, s2, out); break;
        }
    }
    __syncthreads();

    // -------- phase 3: horizontal conv + SSIM + reduce ---------------------
    // thread -> (y = tid%32, x-strip of 8); colsum rows are PITCH=75 apart ->
    // lanes with consecutive y hit distinct banks.
    {
        const int y = tid & 31;
        const int x0 = (tid >> 5) * 8;
        float m[5][8];
#pragma unroll
        for (int q = 0; q < 5; q++)
#pragma unroll
            for (int o = 0; o < 8; o++) m[q][o] = 0.0f;

#pragma unroll
        for (int q = 0; q < 5; q++) {
            const float* cs = &sCS[(q * TH + y) * PITCH + x0];
#pragma unroll
            for (int j = 0; j < 18; j++) {
                float v = cs[j];
#pragma unroll
                for (int o = 0; o < 8; o++) {
                    int w = j - o;
                    if (w >= 0 && w < 11) m[q][o] = fmaf(W[w], v, m[q][o]);
                }
            }
        }

        const float C1 = 1e-4f;   // 0.01^2
        const float C2 = 9e-4f;   // 0.03^2
        float local = 0.0f;
#pragma unroll
        for (int o = 0; o < 8; o++) {
            float m1 = m[0][o], m2 = m[1][o];
            float ex2 = m[2][o], ey2 = m[3][o], exy = m[4][o];
            float m1s = m1 * m1;
            float m2s = m2 * m2;
            float m12 = m1 * m2;
            float s1 = ex2 - m1s;
            float s2 = ey2 - m2s;
            float s12 = exy - m12;
            float num = (2.0f * m12 + C1) * (2.0f * s12 + C2);
            float den = (m1s + m2s + C1) * (s1 + s2 + C2);
            local += num / den;
        }

        // warp reduce
        unsigned mask = 0xffffffffu;
#pragma unroll
        for (int s = 16; s > 0; s >>= 1) local += __shfl_down_sync(mask, local, s);
        if ((tid & 31) == 0) sRed[tid >> 5] = (double)local;
    }
    __syncthreads();
    if (tid == 0) {
        double s = 0.0;
#pragma unroll
        for (int w = 0; w < NTHREADS / 32; w++) s += sRed[w];
        atomicAdd(&g_sum, s);
    }
}

// ---------------------------------------------------------------------------

extern "C" void kernel_launch(void* const* d_in, const int* in_sizes, int n_in,
                              void* d_out, int out_size) {
    const float* img1 = (const float*)d_in[0];
    const float* img2 = (const float*)d_in[1];
    float* out = (float*)d_out;

    const int total = in_sizes[0];                 // 16*3*512*512
    const int planes = total / (IMG_H * IMG_W);    // 48

    const int smem_bytes = (2 * IH + 5 * TH) * PITCH * (int)sizeof(float); // 73200

    static bool attr_set = false;
    if (!attr_set) {
        cudaFuncSetAttribute(ssim_main, cudaFuncAttributeMaxDynamicSharedMemorySize,
                             smem_bytes);
        attr_set = true;
    }

    dim3 grid(IMG_W / TW, IMG_H / TH, planes);     // 8 x 16 x 48
    ssim_zero<<<1, 1>>>();
    ssim_main<<<grid, NTHREADS, smem_bytes>>>(img1, img2);
    ssim_final<<<1, 1>>>(out, 1.0 / (double)total);
}